// round 9
// baseline (speedup 1.0000x reference)
#include <cuda_runtime.h>
#include <cuda_fp16.h>
#include <math.h>
#include <stdint.h>

// Problem constants
#define BB      256
#define NTOK    197
#define CC      768
#define POOL    1024
#define PLEN    8
#define KSEL    8
#define OUTROWS 261
#define PROMPTED_ELEMS ((size_t)BB * OUTROWS * CC)

#define PROJ_M  (POOL * PLEN)   // 8192
#define NCHUNK  8

// Proj GEMM config (fp16 mma.m16n8k16 + ldmatrix)
#define PBM 64
#define PBN 128
#define PBKH 64
#define PNKB (CC / PBKH)               // 12
#define STAGE_BYTES ((PBM + PBN) * 128)  // 24576
#define PSTAGES 3
#define PROJ_SMEM (PSTAGES * STAGE_BYTES)   // 73728 B

// Scratch (device globals)
__device__ float  g_xnorm[BB * CC];
__device__ float  g_pnorm[POOL * CC];
__device__ float  g_sim[BB * POOL];
__device__ float  g_proj[PROJ_M * CC];
__device__ __half g_ah[PROJ_M * CC];
__device__ __half g_wh[CC * CC];
__device__ float  g_msum[BB * NCHUNK * CC];
__device__ int    g_idx[BB * KSEL];
__device__ float  g_topsum[BB];

// ---------------------------------------------------------------------------
__device__ __forceinline__ uint32_t smem_u32(const void* p) {
    uint32_t a;
    asm("{ .reg .u64 t; cvta.to.shared.u64 t, %1; cvt.u32.u64 %0, t; }"
        : "=r"(a) : "l"(p));
    return a;
}

// ---------------------------------------------------------------------------
__global__ void f32_to_f16_kernel(const float* __restrict__ in,
                                  __half* __restrict__ outp, int n8) {
    int i = blockIdx.x * blockDim.x + threadIdx.x;
    if (i < n8) {
        const float4* p = (const float4*)in + (size_t)i * 2;
        float4 a = p[0], b = p[1];
        __half2 h[4];
        h[0] = __floats2half2_rn(a.x, a.y);
        h[1] = __floats2half2_rn(a.z, a.w);
        h[2] = __floats2half2_rn(b.x, b.y);
        h[3] = __floats2half2_rn(b.z, b.w);
        *(uint4*)((char*)outp + (size_t)i * 16) = *(uint4*)h;
    }
}

// ---------------------------------------------------------------------------
// Proj GEMM: C[m,n] = sum_k Ah[m,k]*Wh[n,k] + bias[n] + Ares[m,n]
// ---------------------------------------------------------------------------
__global__ __launch_bounds__(256, 3)
void proj_fp16_kernel(const __half* __restrict__ Ah, const __half* __restrict__ Wh,
                      const float* __restrict__ Ares, const float* __restrict__ bias,
                      float* __restrict__ Cm) {
    extern __shared__ char sm[];
    const uint32_t smbase = smem_u32(sm);

    const int tid  = threadIdx.x;
    const int lane = tid & 31;
    const int wid  = tid >> 5;
    const int wm   = wid >> 2;
    const int wn   = wid & 3;
    const int m0   = blockIdx.y * PBM;
    const int n0   = blockIdx.x * PBN;

    const int crow0 = tid >> 3;
    const int cch   = tid & 7;

    float acc[2][4][4];
    #pragma unroll
    for (int mi = 0; mi < 2; mi++)
        #pragma unroll
        for (int nt = 0; nt < 4; nt++)
            #pragma unroll
            for (int q = 0; q < 4; q++) acc[mi][nt][q] = 0.0f;

    auto issue = [&](int kb) {
        uint32_t stage = smbase + (uint32_t)((kb % PSTAGES) * STAGE_BYTES);
        #pragma unroll
        for (int i = 0; i < 6; i++) {
            int row = crow0 + i * 32;
            const __half* src = (row < PBM)
                ? (Ah + (size_t)(m0 + row) * CC + kb * PBKH + cch * 8)
                : (Wh + (size_t)(n0 + row - PBM) * CC + kb * PBKH + cch * 8);
            uint32_t dst = stage + (uint32_t)row * 128u
                         + (uint32_t)((cch ^ (row & 7)) << 4);
            asm volatile("cp.async.cg.shared.global [%0], [%1], 16;"
                         :: "r"(dst), "l"(src) : "memory");
        }
        asm volatile("cp.async.commit_group;" ::: "memory");
    };

    issue(0);
    issue(1);

    const int q = lane >> 3;
    const int r = lane & 7;

    for (int kb = 0; kb < PNKB; kb++) {
        if (kb + 1 < PNKB) {
            asm volatile("cp.async.wait_group 1;" ::: "memory");
        } else {
            asm volatile("cp.async.wait_group 0;" ::: "memory");
        }
        __syncthreads();
        if (kb + 2 < PNKB) issue(kb + 2);

        const uint32_t Ab = smbase + (uint32_t)((kb % PSTAGES) * STAGE_BYTES);
        const uint32_t Bb = Ab + (uint32_t)(PBM * 128);

        #pragma unroll
        for (int ks = 0; ks < 4; ks++) {
            const int cb = ks * 2 + (q >> 1);
            uint32_t a[2][4];
            #pragma unroll
            for (int mi = 0; mi < 2; mi++) {
                int row = wm * 32 + mi * 16 + (q & 1) * 8 + r;
                uint32_t addr = Ab + (uint32_t)row * 128u
                              + (uint32_t)((cb ^ (row & 7)) << 4);
                asm volatile("ldmatrix.sync.aligned.m8n8.x4.shared.b16 "
                             "{%0,%1,%2,%3}, [%4];"
                             : "=r"(a[mi][0]), "=r"(a[mi][1]),
                               "=r"(a[mi][2]), "=r"(a[mi][3])
                             : "r"(addr));
            }
            uint32_t b[4][2];
            #pragma unroll
            for (int nj = 0; nj < 2; nj++) {
                int row = wn * 32 + nj * 16 + (q & 1) * 8 + r;
                uint32_t addr = Bb + (uint32_t)row * 128u
                              + (uint32_t)((cb ^ (row & 7)) << 4);
                uint32_t r0, r1, r2, r3;
                asm volatile("ldmatrix.sync.aligned.m8n8.x4.shared.b16 "
                             "{%0,%1,%2,%3}, [%4];"
                             : "=r"(r0), "=r"(r1), "=r"(r2), "=r"(r3)
                             : "r"(addr));
                b[nj * 2 + 0][0] = r0; b[nj * 2 + 0][1] = r2;
                b[nj * 2 + 1][0] = r1; b[nj * 2 + 1][1] = r3;
            }
            #pragma unroll
            for (int mi = 0; mi < 2; mi++)
                #pragma unroll
                for (int nt = 0; nt < 4; nt++) {
                    asm volatile(
                        "mma.sync.aligned.m16n8k16.row.col.f32.f16.f16.f32 "
                        "{%0,%1,%2,%3}, {%4,%5,%6,%7}, {%8,%9}, {%0,%1,%2,%3};"
                        : "+f"(acc[mi][nt][0]), "+f"(acc[mi][nt][1]),
                          "+f"(acc[mi][nt][2]), "+f"(acc[mi][nt][3])
                        : "r"(a[mi][0]), "r"(a[mi][1]), "r"(a[mi][2]), "r"(a[mi][3]),
                          "r"(b[nt][0]), "r"(b[nt][1]));
                }
        }
    }

    #pragma unroll
    for (int mi = 0; mi < 2; mi++) {
        int r0 = m0 + wm * 32 + mi * 16 + (lane >> 2);
        int r1 = r0 + 8;
        #pragma unroll
        for (int nt = 0; nt < 4; nt++) {
            int n = n0 + wn * 32 + nt * 8 + (lane & 3) * 2;
            {
                float2 res = *(const float2*)(Ares + (size_t)r0 * CC + n);
                float2 bs  = *(const float2*)(bias + n);
                float2 v;
                v.x = acc[mi][nt][0] + bs.x + res.x;
                v.y = acc[mi][nt][1] + bs.y + res.y;
                *(float2*)(Cm + (size_t)r0 * CC + n) = v;
            }
            {
                float2 res = *(const float2*)(Ares + (size_t)r1 * CC + n);
                float2 bs  = *(const float2*)(bias + n);
                float2 v;
                v.x = acc[mi][nt][2] + bs.x + res.x;
                v.y = acc[mi][nt][3] + bs.y + res.y;
                *(float2*)(Cm + (size_t)r1 * CC + n) = v;
            }
        }
    }
}

// ---------------------------------------------------------------------------
// Fused copy + partial mean (2-way unroll, dual accumulators)
// ---------------------------------------------------------------------------
__global__ void copy_mean_kernel(const float* __restrict__ x, float* __restrict__ out) {
    const int ch = blockIdx.x;
    const int b  = blockIdx.y;
    const int t  = threadIdx.x;

    const int t0 = ch * 25;
    const int t1 = (t0 + 25 < NTOK) ? t0 + 25 : NTOK;

    float4 acc0 = make_float4(0.f, 0.f, 0.f, 0.f);
    float4 acc1 = make_float4(0.f, 0.f, 0.f, 0.f);
    const float4* xb = (const float4*)(x + (size_t)b * NTOK * CC);
    float4* ob = (float4*)(out + (size_t)b * OUTROWS * CC);

    int tok = t0;
    for (; tok + 2 <= t1; tok += 2) {
        float4 v0 = xb[(size_t)tok * (CC / 4) + t];
        float4 v1 = xb[(size_t)(tok + 1) * (CC / 4) + t];
        acc0.x += v0.x; acc0.y += v0.y; acc0.z += v0.z; acc0.w += v0.w;
        acc1.x += v1.x; acc1.y += v1.y; acc1.z += v1.z; acc1.w += v1.w;
        int orow0 = (tok == 0) ? 0 : tok + KSEL * PLEN;
        ob[(size_t)orow0 * (CC / 4) + t] = v0;
        ob[(size_t)(tok + 1 + KSEL * PLEN) * (CC / 4) + t] = v1;
    }
    if (tok < t1) {
        float4 v = xb[(size_t)tok * (CC / 4) + t];
        acc0.x += v.x; acc0.y += v.y; acc0.z += v.z; acc0.w += v.w;
        int orow = (tok == 0) ? 0 : tok + KSEL * PLEN;
        ob[(size_t)orow * (CC / 4) + t] = v;
    }
    acc0.x += acc1.x; acc0.y += acc1.y; acc0.z += acc1.z; acc0.w += acc1.w;
    ((float4*)g_msum)[((size_t)b * NCHUNK + ch) * (CC / 4) + t] = acc0;
}

// ---------------------------------------------------------------------------
__global__ void mean_finish_kernel() {
    int b = blockIdx.x;
    int c = threadIdx.x;
    float s = 0.0f;
    #pragma unroll
    for (int ch = 0; ch < NCHUNK; ch++)
        s += g_msum[((size_t)b * NCHUNK + ch) * CC + c];
    float m = s / (float)NTOK;

    __shared__ float sh[CC];
    sh[c] = m * m;
    __syncthreads();
    if (c < 256) sh[c] += sh[c + 256] + sh[c + 512];
    __syncthreads();
    for (int off = 128; off > 0; off >>= 1) {
        if (c < off) sh[c] += sh[c + off];
        __syncthreads();
    }
    __shared__ float rinv;
    if (c == 0) rinv = rsqrtf(fmaxf(sh[0], 1e-12f));
    __syncthreads();
    g_xnorm[b * CC + c] = m * rinv;
}

// ---------------------------------------------------------------------------
__global__ void key_norm_kernel(const float* __restrict__ pk) {
    int p = blockIdx.x;
    int c = threadIdx.x;
    float v = pk[(size_t)p * CC + c];

    __shared__ float sh[CC];
    sh[c] = v * v;
    __syncthreads();
    if (c < 256) sh[c] += sh[c + 256] + sh[c + 512];
    __syncthreads();
    for (int off = 128; off > 0; off >>= 1) {
        if (c < off) sh[c] += sh[c + off];
        __syncthreads();
    }
    __shared__ float rinv;
    if (c == 0) rinv = rsqrtf(fmaxf(sh[0], 1e-12f));
    __syncthreads();
    g_pnorm[p * CC + c] = v * rinv;
}

// ---------------------------------------------------------------------------
__global__ __launch_bounds__(256)
void sim_gemm_kernel(const float* __restrict__ A, const float* __restrict__ Bm,
                     float* __restrict__ Cm) {
    __shared__ float As[32][33];
    __shared__ float Bs[32][33];

    const int tid = threadIdx.x;
    const int tx = tid & 15;
    const int ty = tid >> 4;
    const int m0 = blockIdx.y * 32;
    const int n0 = blockIdx.x * 32;

    const int lrow = tid >> 3;
    const int lk   = (tid & 7) * 4;

    const float* ag = A  + (size_t)(m0 + lrow) * CC + lk;
    const float* bg = Bm + (size_t)(n0 + lrow) * CC + lk;

    float acc[2][2] = {{0.f,0.f},{0.f,0.f}};

    float4 pa = *(const float4*)(ag);
    float4 pb = *(const float4*)(bg);

    for (int kb = 0; kb < CC / 32; kb++) {
        __syncthreads();
        As[lrow][lk+0]=pa.x; As[lrow][lk+1]=pa.y; As[lrow][lk+2]=pa.z; As[lrow][lk+3]=pa.w;
        Bs[lrow][lk+0]=pb.x; Bs[lrow][lk+1]=pb.y; Bs[lrow][lk+2]=pb.z; Bs[lrow][lk+3]=pb.w;
        __syncthreads();
        if (kb + 1 < CC / 32) {
            pa = *(const float4*)(ag + (kb + 1) * 32);
            pb = *(const float4*)(bg + (kb + 1) * 32);
        }
        #pragma unroll
        for (int kk = 0; kk < 32; kk++) {
            float a0 = As[ty*2+0][kk], a1 = As[ty*2+1][kk];
            float b0 = Bs[tx*2+0][kk], b1 = Bs[tx*2+1][kk];
            acc[0][0] = fmaf(a0,b0,acc[0][0]);
            acc[0][1] = fmaf(a0,b1,acc[0][1]);
            acc[1][0] = fmaf(a1,b0,acc[1][0]);
            acc[1][1] = fmaf(a1,b1,acc[1][1]);
        }
    }
    #pragma unroll
    for (int i = 0; i < 2; i++)
        #pragma unroll
        for (int j = 0; j < 2; j++)
            Cm[(size_t)(m0 + ty*2 + i) * POOL + n0 + tx*2 + j] = acc[i][j];
}

// ---------------------------------------------------------------------------
__global__ void topk_kernel() {
    int b = blockIdx.x;
    int t = threadIdx.x;
    __shared__ float vals[POOL];
    __shared__ float rv[256];
    __shared__ int   ri[256];

    for (int p = t; p < POOL; p += 256) vals[p] = g_sim[b * POOL + p];
    __syncthreads();

    float tsum = 0.0f;
    for (int it = 0; it < KSEL; it++) {
        float bvv = -1e30f; int bii = 0x7fffffff;
        for (int p = t; p < POOL; p += 256) {
            float v = vals[p];
            if (v > bvv || (v == bvv && p < bii)) { bvv = v; bii = p; }
        }
        rv[t] = bvv; ri[t] = bii;
        __syncthreads();
        for (int off = 128; off > 0; off >>= 1) {
            if (t < off) {
                float v2 = rv[t + off]; int i2 = ri[t + off];
                if (v2 > rv[t] || (v2 == rv[t] && i2 < ri[t])) { rv[t] = v2; ri[t] = i2; }
            }
            __syncthreads();
        }
        if (t == 0) {
            g_idx[b * KSEL + it] = ri[0];
            tsum += rv[0];
            vals[ri[0]] = -1e30f;
        }
        __syncthreads();
    }
    if (t == 0) g_topsum[b] = tsum;
}

// ---------------------------------------------------------------------------
__global__ void reduce_sim_kernel(float* __restrict__ out) {
    __shared__ float sh[256];
    int t = threadIdx.x;
    sh[t] = g_topsum[t];
    __syncthreads();
    for (int off = 128; off > 0; off >>= 1) {
        if (t < off) sh[t] += sh[t + off];
        __syncthreads();
    }
    if (t == 0) out[PROMPTED_ELEMS] = sh[0] / (float)BB;
}

// ---------------------------------------------------------------------------
__global__ void gather_kernel(float* __restrict__ out) {
    int j = blockIdx.x;
    int b = blockIdx.y;
    int t = threadIdx.x;

    int pid = g_idx[b * KSEL + (j >> 3)];
    const float4* src = (const float4*)(g_proj + ((size_t)pid * PLEN + (j & 7)) * CC);
    float4 v = src[t];
    ((float4*)(out + ((size_t)b * OUTROWS + 1 + j) * CC))[t] = v;
}

// ---------------------------------------------------------------------------
extern "C" void kernel_launch(void* const* d_in, const int* in_sizes, int n_in,
                              void* d_out, int out_size) {
    const float* x_embed = (const float*)d_in[0];
    const float* prompt  = (const float*)d_in[1];
    const float* pkey    = (const float*)d_in[2];
    const float* proj_w  = (const float*)d_in[3];
    const float* proj_b  = (const float*)d_in[4];
    float* out = (float*)d_out;

    float *p_xnorm, *p_pnorm, *p_sim, *p_proj;
    __half *p_ah, *p_wh;
    cudaGetSymbolAddress((void**)&p_xnorm, g_xnorm);
    cudaGetSymbolAddress((void**)&p_pnorm, g_pnorm);
    cudaGetSymbolAddress((void**)&p_sim,   g_sim);
    cudaGetSymbolAddress((void**)&p_proj,  g_proj);
    cudaGetSymbolAddress((void**)&p_ah,    g_ah);
    cudaGetSymbolAddress((void**)&p_wh,    g_wh);

    // One-time resources (handles only; no device memory)
    static cudaStream_t sA = nullptr, sB = nullptr;
    static cudaEvent_t  evFork = nullptr, evProj = nullptr, evDone = nullptr;
    if (sA == nullptr) {
        cudaStreamCreateWithFlags(&sA, cudaStreamNonBlocking);
        cudaStreamCreateWithFlags(&sB, cudaStreamNonBlocking);
        cudaEventCreateWithFlags(&evFork, cudaEventDisableTiming);
        cudaEventCreateWithFlags(&evProj, cudaEventDisableTiming);
        cudaEventCreateWithFlags(&evDone, cudaEventDisableTiming);
        cudaFuncSetAttribute(proj_fp16_kernel,
                             cudaFuncAttributeMaxDynamicSharedMemorySize, PROJ_SMEM);
    }

    // ---- fork BOTH created streams off the capture-origin (legacy) stream.
    // No kernels go to stream 0, so legacy-stream implicit syncs can't
    // serialize the two branches.
    cudaEventRecord(evFork, 0);
    cudaStreamWaitEvent(sA, evFork, 0);
    cudaStreamWaitEvent(sB, evFork, 0);

    // ===== Stream A: tensor/L1-bound chain (f16 convs + proj) =====
    {
        int n8a = PROJ_M * CC / 8;
        f32_to_f16_kernel<<<(n8a + 255) / 256, 256, 0, sA>>>(prompt, p_ah, n8a);
        int n8w = CC * CC / 8;
        f32_to_f16_kernel<<<(n8w + 255) / 256, 256, 0, sA>>>(proj_w, p_wh, n8w);
        dim3 grid(CC / PBN, PROJ_M / PBM);
        proj_fp16_kernel<<<grid, 256, PROJ_SMEM, sA>>>(p_ah, p_wh, prompt, proj_b, p_proj);
        cudaEventRecord(evProj, sA);
    }

    // ===== Stream B: DRAM-bound critical path =====
    key_norm_kernel<<<POOL, CC, 0, sB>>>(pkey);
    {
        dim3 grid(NCHUNK, BB);
        copy_mean_kernel<<<grid, 192, 0, sB>>>(x_embed, out);
    }
    mean_finish_kernel<<<BB, CC, 0, sB>>>();
    {
        dim3 grid(POOL / 32, BB / 32);
        sim_gemm_kernel<<<grid, 256, 0, sB>>>(p_xnorm, p_pnorm, p_sim);
    }
    topk_kernel<<<BB, 256, 0, sB>>>();
    reduce_sim_kernel<<<1, 256, 0, sB>>>(out);

    // gather needs g_proj (stream A) and g_idx (stream B) -> run on sB
    cudaStreamWaitEvent(sB, evProj, 0);
    {
        dim3 grid(KSEL * PLEN, BB);
        gather_kernel<<<grid, 192, 0, sB>>>(out);
    }

    // ---- join everything back to the origin stream before capture ends ----
    cudaEventRecord(evDone, sB);
    cudaStreamWaitEvent(0, evDone, 0);
}

// round 10
// speedup vs baseline: 1.0037x; 1.0037x over previous
#include <cuda_runtime.h>
#include <cuda_fp16.h>
#include <math.h>
#include <stdint.h>

// Problem constants
#define BB      256
#define NTOK    197
#define CC      768
#define POOL    1024
#define PLEN    8
#define KSEL    8
#define OUTROWS 261
#define PROMPTED_ELEMS ((size_t)BB * OUTROWS * CC)

#define PROJ_M  (POOL * PLEN)   // 8192
#define NCHUNK  8

// Proj GEMM config (fp16 mma.m16n8k16 + ldmatrix)
#define PBM 64
#define PBN 128
#define PBKH 64
#define PNKB (CC / PBKH)               // 12
#define STAGE_BYTES ((PBM + PBN) * 128)  // 24576
#define PSTAGES 3
#define PROJ_SMEM (PSTAGES * STAGE_BYTES)   // 73728 B

// Scratch (device globals)
__device__ float  g_xnorm[BB * CC];
__device__ float  g_pnorm[POOL * CC];
__device__ float  g_sim[BB * POOL];
__device__ float  g_proj[PROJ_M * CC];
__device__ __half g_ah[PROJ_M * CC];
__device__ __half g_wh[CC * CC];
__device__ float  g_msum[BB * NCHUNK * CC];
__device__ int    g_idx[BB * KSEL];
__device__ float  g_topsum[BB];

// ---------------------------------------------------------------------------
__device__ __forceinline__ uint32_t smem_u32(const void* p) {
    uint32_t a;
    asm("{ .reg .u64 t; cvta.to.shared.u64 t, %1; cvt.u32.u64 %0, t; }"
        : "=r"(a) : "l"(p));
    return a;
}

// ---------------------------------------------------------------------------
__global__ void f32_to_f16_kernel(const float* __restrict__ in,
                                  __half* __restrict__ outp, int n8) {
    int i = blockIdx.x * blockDim.x + threadIdx.x;
    if (i < n8) {
        const float4* p = (const float4*)in + (size_t)i * 2;
        float4 a = p[0], b = p[1];
        __half2 h[4];
        h[0] = __floats2half2_rn(a.x, a.y);
        h[1] = __floats2half2_rn(a.z, a.w);
        h[2] = __floats2half2_rn(b.x, b.y);
        h[3] = __floats2half2_rn(b.z, b.w);
        *(uint4*)((char*)outp + (size_t)i * 16) = *(uint4*)h;
    }
}

// ---------------------------------------------------------------------------
// Proj GEMM: C[m,n] = sum_k Ah[m,k]*Wh[n,k] + bias[n] + Ares[m,n]
// ---------------------------------------------------------------------------
__global__ __launch_bounds__(256, 3)
void proj_fp16_kernel(const __half* __restrict__ Ah, const __half* __restrict__ Wh,
                      const float* __restrict__ Ares, const float* __restrict__ bias,
                      float* __restrict__ Cm) {
    extern __shared__ char sm[];
    const uint32_t smbase = smem_u32(sm);

    const int tid  = threadIdx.x;
    const int lane = tid & 31;
    const int wid  = tid >> 5;
    const int wm   = wid >> 2;
    const int wn   = wid & 3;
    const int m0   = blockIdx.y * PBM;
    const int n0   = blockIdx.x * PBN;

    const int crow0 = tid >> 3;
    const int cch   = tid & 7;

    float acc[2][4][4];
    #pragma unroll
    for (int mi = 0; mi < 2; mi++)
        #pragma unroll
        for (int nt = 0; nt < 4; nt++)
            #pragma unroll
            for (int q = 0; q < 4; q++) acc[mi][nt][q] = 0.0f;

    auto issue = [&](int kb) {
        uint32_t stage = smbase + (uint32_t)((kb % PSTAGES) * STAGE_BYTES);
        #pragma unroll
        for (int i = 0; i < 6; i++) {
            int row = crow0 + i * 32;
            const __half* src = (row < PBM)
                ? (Ah + (size_t)(m0 + row) * CC + kb * PBKH + cch * 8)
                : (Wh + (size_t)(n0 + row - PBM) * CC + kb * PBKH + cch * 8);
            uint32_t dst = stage + (uint32_t)row * 128u
                         + (uint32_t)((cch ^ (row & 7)) << 4);
            asm volatile("cp.async.cg.shared.global [%0], [%1], 16;"
                         :: "r"(dst), "l"(src) : "memory");
        }
        asm volatile("cp.async.commit_group;" ::: "memory");
    };

    issue(0);
    issue(1);

    const int q = lane >> 3;
    const int r = lane & 7;

    for (int kb = 0; kb < PNKB; kb++) {
        if (kb + 1 < PNKB) {
            asm volatile("cp.async.wait_group 1;" ::: "memory");
        } else {
            asm volatile("cp.async.wait_group 0;" ::: "memory");
        }
        __syncthreads();
        if (kb + 2 < PNKB) issue(kb + 2);

        const uint32_t Ab = smbase + (uint32_t)((kb % PSTAGES) * STAGE_BYTES);
        const uint32_t Bb = Ab + (uint32_t)(PBM * 128);

        #pragma unroll
        for (int ks = 0; ks < 4; ks++) {
            const int cb = ks * 2 + (q >> 1);
            uint32_t a[2][4];
            #pragma unroll
            for (int mi = 0; mi < 2; mi++) {
                int row = wm * 32 + mi * 16 + (q & 1) * 8 + r;
                uint32_t addr = Ab + (uint32_t)row * 128u
                              + (uint32_t)((cb ^ (row & 7)) << 4);
                asm volatile("ldmatrix.sync.aligned.m8n8.x4.shared.b16 "
                             "{%0,%1,%2,%3}, [%4];"
                             : "=r"(a[mi][0]), "=r"(a[mi][1]),
                               "=r"(a[mi][2]), "=r"(a[mi][3])
                             : "r"(addr));
            }
            uint32_t b[4][2];
            #pragma unroll
            for (int nj = 0; nj < 2; nj++) {
                int row = wn * 32 + nj * 16 + (q & 1) * 8 + r;
                uint32_t addr = Bb + (uint32_t)row * 128u
                              + (uint32_t)((cb ^ (row & 7)) << 4);
                uint32_t r0, r1, r2, r3;
                asm volatile("ldmatrix.sync.aligned.m8n8.x4.shared.b16 "
                             "{%0,%1,%2,%3}, [%4];"
                             : "=r"(r0), "=r"(r1), "=r"(r2), "=r"(r3)
                             : "r"(addr));
                b[nj * 2 + 0][0] = r0; b[nj * 2 + 0][1] = r2;
                b[nj * 2 + 1][0] = r1; b[nj * 2 + 1][1] = r3;
            }
            #pragma unroll
            for (int mi = 0; mi < 2; mi++)
                #pragma unroll
                for (int nt = 0; nt < 4; nt++) {
                    asm volatile(
                        "mma.sync.aligned.m16n8k16.row.col.f32.f16.f16.f32 "
                        "{%0,%1,%2,%3}, {%4,%5,%6,%7}, {%8,%9}, {%0,%1,%2,%3};"
                        : "+f"(acc[mi][nt][0]), "+f"(acc[mi][nt][1]),
                          "+f"(acc[mi][nt][2]), "+f"(acc[mi][nt][3])
                        : "r"(a[mi][0]), "r"(a[mi][1]), "r"(a[mi][2]), "r"(a[mi][3]),
                          "r"(b[nt][0]), "r"(b[nt][1]));
                }
        }
    }

    #pragma unroll
    for (int mi = 0; mi < 2; mi++) {
        int r0 = m0 + wm * 32 + mi * 16 + (lane >> 2);
        int r1 = r0 + 8;
        #pragma unroll
        for (int nt = 0; nt < 4; nt++) {
            int n = n0 + wn * 32 + nt * 8 + (lane & 3) * 2;
            {
                float2 res = *(const float2*)(Ares + (size_t)r0 * CC + n);
                float2 bs  = *(const float2*)(bias + n);
                float2 v;
                v.x = acc[mi][nt][0] + bs.x + res.x;
                v.y = acc[mi][nt][1] + bs.y + res.y;
                *(float2*)(Cm + (size_t)r0 * CC + n) = v;
            }
            {
                float2 res = *(const float2*)(Ares + (size_t)r1 * CC + n);
                float2 bs  = *(const float2*)(bias + n);
                float2 v;
                v.x = acc[mi][nt][2] + bs.x + res.x;
                v.y = acc[mi][nt][3] + bs.y + res.y;
                *(float2*)(Cm + (size_t)r1 * CC + n) = v;
            }
        }
    }
}

// ---------------------------------------------------------------------------
// Fused copy + partial mean (2-way unroll, dual accumulators)
// ---------------------------------------------------------------------------
__global__ void copy_mean_kernel(const float* __restrict__ x, float* __restrict__ out) {
    const int ch = blockIdx.x;
    const int b  = blockIdx.y;
    const int t  = threadIdx.x;

    const int t0 = ch * 25;
    const int t1 = (t0 + 25 < NTOK) ? t0 + 25 : NTOK;

    float4 acc0 = make_float4(0.f, 0.f, 0.f, 0.f);
    float4 acc1 = make_float4(0.f, 0.f, 0.f, 0.f);
    const float4* xb = (const float4*)(x + (size_t)b * NTOK * CC);
    float4* ob = (float4*)(out + (size_t)b * OUTROWS * CC);

    int tok = t0;
    for (; tok + 2 <= t1; tok += 2) {
        float4 v0 = xb[(size_t)tok * (CC / 4) + t];
        float4 v1 = xb[(size_t)(tok + 1) * (CC / 4) + t];
        acc0.x += v0.x; acc0.y += v0.y; acc0.z += v0.z; acc0.w += v0.w;
        acc1.x += v1.x; acc1.y += v1.y; acc1.z += v1.z; acc1.w += v1.w;
        int orow0 = (tok == 0) ? 0 : tok + KSEL * PLEN;
        ob[(size_t)orow0 * (CC / 4) + t] = v0;
        ob[(size_t)(tok + 1 + KSEL * PLEN) * (CC / 4) + t] = v1;
    }
    if (tok < t1) {
        float4 v = xb[(size_t)tok * (CC / 4) + t];
        acc0.x += v.x; acc0.y += v.y; acc0.z += v.z; acc0.w += v.w;
        int orow = (tok == 0) ? 0 : tok + KSEL * PLEN;
        ob[(size_t)orow * (CC / 4) + t] = v;
    }
    acc0.x += acc1.x; acc0.y += acc1.y; acc0.z += acc1.z; acc0.w += acc1.w;
    ((float4*)g_msum)[((size_t)b * NCHUNK + ch) * (CC / 4) + t] = acc0;
}

// ---------------------------------------------------------------------------
__global__ void mean_finish_kernel() {
    int b = blockIdx.x;
    int c = threadIdx.x;
    float s = 0.0f;
    #pragma unroll
    for (int ch = 0; ch < NCHUNK; ch++)
        s += g_msum[((size_t)b * NCHUNK + ch) * CC + c];
    float m = s / (float)NTOK;

    __shared__ float sh[CC];
    sh[c] = m * m;
    __syncthreads();
    if (c < 256) sh[c] += sh[c + 256] + sh[c + 512];
    __syncthreads();
    for (int off = 128; off > 0; off >>= 1) {
        if (c < off) sh[c] += sh[c + off];
        __syncthreads();
    }
    __shared__ float rinv;
    if (c == 0) rinv = rsqrtf(fmaxf(sh[0], 1e-12f));
    __syncthreads();
    g_xnorm[b * CC + c] = m * rinv;
}

// ---------------------------------------------------------------------------
__global__ void key_norm_kernel(const float* __restrict__ pk) {
    int p = blockIdx.x;
    int c = threadIdx.x;
    float v = pk[(size_t)p * CC + c];

    __shared__ float sh[CC];
    sh[c] = v * v;
    __syncthreads();
    if (c < 256) sh[c] += sh[c + 256] + sh[c + 512];
    __syncthreads();
    for (int off = 128; off > 0; off >>= 1) {
        if (c < off) sh[c] += sh[c + off];
        __syncthreads();
    }
    __shared__ float rinv;
    if (c == 0) rinv = rsqrtf(fmaxf(sh[0], 1e-12f));
    __syncthreads();
    g_pnorm[p * CC + c] = v * rinv;
}

// ---------------------------------------------------------------------------
__global__ __launch_bounds__(256)
void sim_gemm_kernel(const float* __restrict__ A, const float* __restrict__ Bm,
                     float* __restrict__ Cm) {
    __shared__ float As[32][33];
    __shared__ float Bs[32][33];

    const int tid = threadIdx.x;
    const int tx = tid & 15;
    const int ty = tid >> 4;
    const int m0 = blockIdx.y * 32;
    const int n0 = blockIdx.x * 32;

    const int lrow = tid >> 3;
    const int lk   = (tid & 7) * 4;

    const float* ag = A  + (size_t)(m0 + lrow) * CC + lk;
    const float* bg = Bm + (size_t)(n0 + lrow) * CC + lk;

    float acc[2][2] = {{0.f,0.f},{0.f,0.f}};

    float4 pa = *(const float4*)(ag);
    float4 pb = *(const float4*)(bg);

    for (int kb = 0; kb < CC / 32; kb++) {
        __syncthreads();
        As[lrow][lk+0]=pa.x; As[lrow][lk+1]=pa.y; As[lrow][lk+2]=pa.z; As[lrow][lk+3]=pa.w;
        Bs[lrow][lk+0]=pb.x; Bs[lrow][lk+1]=pb.y; Bs[lrow][lk+2]=pb.z; Bs[lrow][lk+3]=pb.w;
        __syncthreads();
        if (kb + 1 < CC / 32) {
            pa = *(const float4*)(ag + (kb + 1) * 32);
            pb = *(const float4*)(bg + (kb + 1) * 32);
        }
        #pragma unroll
        for (int kk = 0; kk < 32; kk++) {
            float a0 = As[ty*2+0][kk], a1 = As[ty*2+1][kk];
            float b0 = Bs[tx*2+0][kk], b1 = Bs[tx*2+1][kk];
            acc[0][0] = fmaf(a0,b0,acc[0][0]);
            acc[0][1] = fmaf(a0,b1,acc[0][1]);
            acc[1][0] = fmaf(a1,b0,acc[1][0]);
            acc[1][1] = fmaf(a1,b1,acc[1][1]);
        }
    }
    #pragma unroll
    for (int i = 0; i < 2; i++)
        #pragma unroll
        for (int j = 0; j < 2; j++)
            Cm[(size_t)(m0 + ty*2 + i) * POOL + n0 + tx*2 + j] = acc[i][j];
}

// ---------------------------------------------------------------------------
__global__ void topk_kernel() {
    int b = blockIdx.x;
    int t = threadIdx.x;
    __shared__ float vals[POOL];
    __shared__ float rv[256];
    __shared__ int   ri[256];

    for (int p = t; p < POOL; p += 256) vals[p] = g_sim[b * POOL + p];
    __syncthreads();

    float tsum = 0.0f;
    for (int it = 0; it < KSEL; it++) {
        float bvv = -1e30f; int bii = 0x7fffffff;
        for (int p = t; p < POOL; p += 256) {
            float v = vals[p];
            if (v > bvv || (v == bvv && p < bii)) { bvv = v; bii = p; }
        }
        rv[t] = bvv; ri[t] = bii;
        __syncthreads();
        for (int off = 128; off > 0; off >>= 1) {
            if (t < off) {
                float v2 = rv[t + off]; int i2 = ri[t + off];
                if (v2 > rv[t] || (v2 == rv[t] && i2 < ri[t])) { rv[t] = v2; ri[t] = i2; }
            }
            __syncthreads();
        }
        if (t == 0) {
            g_idx[b * KSEL + it] = ri[0];
            tsum += rv[0];
            vals[ri[0]] = -1e30f;
        }
        __syncthreads();
    }
    if (t == 0) g_topsum[b] = tsum;
}

// ---------------------------------------------------------------------------
__global__ void reduce_sim_kernel(float* __restrict__ out) {
    __shared__ float sh[256];
    int t = threadIdx.x;
    sh[t] = g_topsum[t];
    __syncthreads();
    for (int off = 128; off > 0; off >>= 1) {
        if (t < off) sh[t] += sh[t + off];
        __syncthreads();
    }
    if (t == 0) out[PROMPTED_ELEMS] = sh[0] / (float)BB;
}

// ---------------------------------------------------------------------------
__global__ void gather_kernel(float* __restrict__ out) {
    int j = blockIdx.x;
    int b = blockIdx.y;
    int t = threadIdx.x;

    int pid = g_idx[b * KSEL + (j >> 3)];
    const float4* src = (const float4*)(g_proj + ((size_t)pid * PLEN + (j & 7)) * CC);
    float4 v = src[t];
    ((float4*)(out + ((size_t)b * OUTROWS + 1 + j) * CC))[t] = v;
}

// ---------------------------------------------------------------------------
extern "C" void kernel_launch(void* const* d_in, const int* in_sizes, int n_in,
                              void* d_out, int out_size) {
    const float* x_embed = (const float*)d_in[0];
    const float* prompt  = (const float*)d_in[1];
    const float* pkey    = (const float*)d_in[2];
    const float* proj_w  = (const float*)d_in[3];
    const float* proj_b  = (const float*)d_in[4];
    float* out = (float*)d_out;

    float *p_xnorm, *p_pnorm, *p_sim, *p_proj;
    __half *p_ah, *p_wh;
    cudaGetSymbolAddress((void**)&p_xnorm, g_xnorm);
    cudaGetSymbolAddress((void**)&p_pnorm, g_pnorm);
    cudaGetSymbolAddress((void**)&p_sim,   g_sim);
    cudaGetSymbolAddress((void**)&p_proj,  g_proj);
    cudaGetSymbolAddress((void**)&p_ah,    g_ah);
    cudaGetSymbolAddress((void**)&p_wh,    g_wh);

    // One-time resources (handles only; no device memory)
    static cudaStream_t sA = nullptr, sB = nullptr;
    static cudaEvent_t  evFork = nullptr, evProj = nullptr, evDone = nullptr;
    if (sA == nullptr) {
        cudaStreamCreateWithFlags(&sA, cudaStreamNonBlocking);
        cudaStreamCreateWithFlags(&sB, cudaStreamNonBlocking);
        cudaEventCreateWithFlags(&evFork, cudaEventDisableTiming);
        cudaEventCreateWithFlags(&evProj, cudaEventDisableTiming);
        cudaEventCreateWithFlags(&evDone, cudaEventDisableTiming);
        cudaFuncSetAttribute(proj_fp16_kernel,
                             cudaFuncAttributeMaxDynamicSharedMemorySize, PROJ_SMEM);
    }

    // ---- fork BOTH created streams off the capture-origin (legacy) stream.
    // No kernels go to stream 0, so legacy-stream implicit syncs can't
    // serialize the two branches.
    cudaEventRecord(evFork, 0);
    cudaStreamWaitEvent(sA, evFork, 0);
    cudaStreamWaitEvent(sB, evFork, 0);

    // ===== Stream A: tensor/L1-bound chain (f16 convs + proj) =====
    {
        int n8a = PROJ_M * CC / 8;
        f32_to_f16_kernel<<<(n8a + 255) / 256, 256, 0, sA>>>(prompt, p_ah, n8a);
        int n8w = CC * CC / 8;
        f32_to_f16_kernel<<<(n8w + 255) / 256, 256, 0, sA>>>(proj_w, p_wh, n8w);
        dim3 grid(CC / PBN, PROJ_M / PBM);
        proj_fp16_kernel<<<grid, 256, PROJ_SMEM, sA>>>(p_ah, p_wh, prompt, proj_b, p_proj);
        cudaEventRecord(evProj, sA);
    }

    // ===== Stream B: DRAM-bound critical path =====
    key_norm_kernel<<<POOL, CC, 0, sB>>>(pkey);
    {
        dim3 grid(NCHUNK, BB);
        copy_mean_kernel<<<grid, 192, 0, sB>>>(x_embed, out);
    }
    mean_finish_kernel<<<BB, CC, 0, sB>>>();
    {
        dim3 grid(POOL / 32, BB / 32);
        sim_gemm_kernel<<<grid, 256, 0, sB>>>(p_xnorm, p_pnorm, p_sim);
    }
    topk_kernel<<<BB, 256, 0, sB>>>();
    reduce_sim_kernel<<<1, 256, 0, sB>>>(out);

    // gather needs g_proj (stream A) and g_idx (stream B) -> run on sB
    cudaStreamWaitEvent(sB, evProj, 0);
    {
        dim3 grid(KSEL * PLEN, BB);
        gather_kernel<<<grid, 192, 0, sB>>>(out);
    }

    // ---- join everything back to the origin stream before capture ends ----
    cudaEventRecord(evDone, sB);
    cudaStreamWaitEvent(0, evDone, 0);
}

// round 11
// speedup vs baseline: 1.0043x; 1.0006x over previous
#include <cuda_runtime.h>
#include <cuda_fp16.h>
#include <math.h>
#include <stdint.h>

// Problem constants
#define BB      256
#define NTOK    197
#define CC      768
#define POOL    1024
#define PLEN    8
#define KSEL    8
#define OUTROWS 261
#define PROMPTED_ELEMS ((size_t)BB * OUTROWS * CC)

#define PROJ_M  (POOL * PLEN)   // 8192
#define NCHUNK  8

// Proj GEMM config (fp16 mma.m16n8k16 + ldmatrix)
#define PBM 64
#define PBN 128
#define PBKH 64
#define PNKB (CC / PBKH)               // 12
#define STAGE_BYTES ((PBM + PBN) * 128)  // 24576
#define PSTAGES 3
#define PROJ_SMEM (PSTAGES * STAGE_BYTES)   // 73728 B

// Scratch (device globals)
__device__ float  g_xnorm[BB * CC];
__device__ float  g_pnorm[POOL * CC];
__device__ float  g_sim[BB * POOL];
__device__ float  g_proj[PROJ_M * CC];
__device__ __half g_ah[PROJ_M * CC];
__device__ __half g_wh[CC * CC];
__device__ float  g_msum[BB * NCHUNK * CC];
__device__ int    g_idx[BB * KSEL];
__device__ float  g_topsum[BB];

// ---------------------------------------------------------------------------
__device__ __forceinline__ uint32_t smem_u32(const void* p) {
    uint32_t a;
    asm("{ .reg .u64 t; cvta.to.shared.u64 t, %1; cvt.u32.u64 %0, t; }"
        : "=r"(a) : "l"(p));
    return a;
}

// ---------------------------------------------------------------------------
__global__ void f32_to_f16_kernel(const float* __restrict__ in,
                                  __half* __restrict__ outp, int n8) {
    int i = blockIdx.x * blockDim.x + threadIdx.x;
    if (i < n8) {
        const float4* p = (const float4*)in + (size_t)i * 2;
        float4 a = p[0], b = p[1];
        __half2 h[4];
        h[0] = __floats2half2_rn(a.x, a.y);
        h[1] = __floats2half2_rn(a.z, a.w);
        h[2] = __floats2half2_rn(b.x, b.y);
        h[3] = __floats2half2_rn(b.z, b.w);
        *(uint4*)((char*)outp + (size_t)i * 16) = *(uint4*)h;
    }
}

// ---------------------------------------------------------------------------
// Proj GEMM: C[m,n] = sum_k Ah[m,k]*Wh[n,k] + bias[n] + Ares[m,n]
// ---------------------------------------------------------------------------
__global__ __launch_bounds__(256, 3)
void proj_fp16_kernel(const __half* __restrict__ Ah, const __half* __restrict__ Wh,
                      const float* __restrict__ Ares, const float* __restrict__ bias,
                      float* __restrict__ Cm) {
    extern __shared__ char sm[];
    const uint32_t smbase = smem_u32(sm);

    const int tid  = threadIdx.x;
    const int lane = tid & 31;
    const int wid  = tid >> 5;
    const int wm   = wid >> 2;
    const int wn   = wid & 3;
    const int m0   = blockIdx.y * PBM;
    const int n0   = blockIdx.x * PBN;

    const int crow0 = tid >> 3;
    const int cch   = tid & 7;

    float acc[2][4][4];
    #pragma unroll
    for (int mi = 0; mi < 2; mi++)
        #pragma unroll
        for (int nt = 0; nt < 4; nt++)
            #pragma unroll
            for (int q = 0; q < 4; q++) acc[mi][nt][q] = 0.0f;

    auto issue = [&](int kb) {
        uint32_t stage = smbase + (uint32_t)((kb % PSTAGES) * STAGE_BYTES);
        #pragma unroll
        for (int i = 0; i < 6; i++) {
            int row = crow0 + i * 32;
            const __half* src = (row < PBM)
                ? (Ah + (size_t)(m0 + row) * CC + kb * PBKH + cch * 8)
                : (Wh + (size_t)(n0 + row - PBM) * CC + kb * PBKH + cch * 8);
            uint32_t dst = stage + (uint32_t)row * 128u
                         + (uint32_t)((cch ^ (row & 7)) << 4);
            asm volatile("cp.async.cg.shared.global [%0], [%1], 16;"
                         :: "r"(dst), "l"(src) : "memory");
        }
        asm volatile("cp.async.commit_group;" ::: "memory");
    };

    issue(0);
    issue(1);

    const int q = lane >> 3;
    const int r = lane & 7;

    for (int kb = 0; kb < PNKB; kb++) {
        if (kb + 1 < PNKB) {
            asm volatile("cp.async.wait_group 1;" ::: "memory");
        } else {
            asm volatile("cp.async.wait_group 0;" ::: "memory");
        }
        __syncthreads();
        if (kb + 2 < PNKB) issue(kb + 2);

        const uint32_t Ab = smbase + (uint32_t)((kb % PSTAGES) * STAGE_BYTES);
        const uint32_t Bb = Ab + (uint32_t)(PBM * 128);

        #pragma unroll
        for (int ks = 0; ks < 4; ks++) {
            const int cb = ks * 2 + (q >> 1);
            uint32_t a[2][4];
            #pragma unroll
            for (int mi = 0; mi < 2; mi++) {
                int row = wm * 32 + mi * 16 + (q & 1) * 8 + r;
                uint32_t addr = Ab + (uint32_t)row * 128u
                              + (uint32_t)((cb ^ (row & 7)) << 4);
                asm volatile("ldmatrix.sync.aligned.m8n8.x4.shared.b16 "
                             "{%0,%1,%2,%3}, [%4];"
                             : "=r"(a[mi][0]), "=r"(a[mi][1]),
                               "=r"(a[mi][2]), "=r"(a[mi][3])
                             : "r"(addr));
            }
            uint32_t b[4][2];
            #pragma unroll
            for (int nj = 0; nj < 2; nj++) {
                int row = wn * 32 + nj * 16 + (q & 1) * 8 + r;
                uint32_t addr = Bb + (uint32_t)row * 128u
                              + (uint32_t)((cb ^ (row & 7)) << 4);
                uint32_t r0, r1, r2, r3;
                asm volatile("ldmatrix.sync.aligned.m8n8.x4.shared.b16 "
                             "{%0,%1,%2,%3}, [%4];"
                             : "=r"(r0), "=r"(r1), "=r"(r2), "=r"(r3)
                             : "r"(addr));
                b[nj * 2 + 0][0] = r0; b[nj * 2 + 0][1] = r2;
                b[nj * 2 + 1][0] = r1; b[nj * 2 + 1][1] = r3;
            }
            #pragma unroll
            for (int mi = 0; mi < 2; mi++)
                #pragma unroll
                for (int nt = 0; nt < 4; nt++) {
                    asm volatile(
                        "mma.sync.aligned.m16n8k16.row.col.f32.f16.f16.f32 "
                        "{%0,%1,%2,%3}, {%4,%5,%6,%7}, {%8,%9}, {%0,%1,%2,%3};"
                        : "+f"(acc[mi][nt][0]), "+f"(acc[mi][nt][1]),
                          "+f"(acc[mi][nt][2]), "+f"(acc[mi][nt][3])
                        : "r"(a[mi][0]), "r"(a[mi][1]), "r"(a[mi][2]), "r"(a[mi][3]),
                          "r"(b[nt][0]), "r"(b[nt][1]));
                }
        }
    }

    #pragma unroll
    for (int mi = 0; mi < 2; mi++) {
        int r0 = m0 + wm * 32 + mi * 16 + (lane >> 2);
        int r1 = r0 + 8;
        #pragma unroll
        for (int nt = 0; nt < 4; nt++) {
            int n = n0 + wn * 32 + nt * 8 + (lane & 3) * 2;
            {
                float2 res = *(const float2*)(Ares + (size_t)r0 * CC + n);
                float2 bs  = *(const float2*)(bias + n);
                float2 v;
                v.x = acc[mi][nt][0] + bs.x + res.x;
                v.y = acc[mi][nt][1] + bs.y + res.y;
                *(float2*)(Cm + (size_t)r0 * CC + n) = v;
            }
            {
                float2 res = *(const float2*)(Ares + (size_t)r1 * CC + n);
                float2 bs  = *(const float2*)(bias + n);
                float2 v;
                v.x = acc[mi][nt][2] + bs.x + res.x;
                v.y = acc[mi][nt][3] + bs.y + res.y;
                *(float2*)(Cm + (size_t)r1 * CC + n) = v;
            }
        }
    }
}

// ---------------------------------------------------------------------------
// Fused copy + partial mean (2-way unroll, dual accumulators)
// ---------------------------------------------------------------------------
__global__ void copy_mean_kernel(const float* __restrict__ x, float* __restrict__ out) {
    const int ch = blockIdx.x;
    const int b  = blockIdx.y;
    const int t  = threadIdx.x;

    const int t0 = ch * 25;
    const int t1 = (t0 + 25 < NTOK) ? t0 + 25 : NTOK;

    float4 acc0 = make_float4(0.f, 0.f, 0.f, 0.f);
    float4 acc1 = make_float4(0.f, 0.f, 0.f, 0.f);
    const float4* xb = (const float4*)(x + (size_t)b * NTOK * CC);
    float4* ob = (float4*)(out + (size_t)b * OUTROWS * CC);

    int tok = t0;
    for (; tok + 2 <= t1; tok += 2) {
        float4 v0 = xb[(size_t)tok * (CC / 4) + t];
        float4 v1 = xb[(size_t)(tok + 1) * (CC / 4) + t];
        acc0.x += v0.x; acc0.y += v0.y; acc0.z += v0.z; acc0.w += v0.w;
        acc1.x += v1.x; acc1.y += v1.y; acc1.z += v1.z; acc1.w += v1.w;
        int orow0 = (tok == 0) ? 0 : tok + KSEL * PLEN;
        ob[(size_t)orow0 * (CC / 4) + t] = v0;
        ob[(size_t)(tok + 1 + KSEL * PLEN) * (CC / 4) + t] = v1;
    }
    if (tok < t1) {
        float4 v = xb[(size_t)tok * (CC / 4) + t];
        acc0.x += v.x; acc0.y += v.y; acc0.z += v.z; acc0.w += v.w;
        int orow = (tok == 0) ? 0 : tok + KSEL * PLEN;
        ob[(size_t)orow * (CC / 4) + t] = v;
    }
    acc0.x += acc1.x; acc0.y += acc1.y; acc0.z += acc1.z; acc0.w += acc1.w;
    ((float4*)g_msum)[((size_t)b * NCHUNK + ch) * (CC / 4) + t] = acc0;
}

// ---------------------------------------------------------------------------
__global__ void mean_finish_kernel() {
    int b = blockIdx.x;
    int c = threadIdx.x;
    float s = 0.0f;
    #pragma unroll
    for (int ch = 0; ch < NCHUNK; ch++)
        s += g_msum[((size_t)b * NCHUNK + ch) * CC + c];
    float m = s / (float)NTOK;

    __shared__ float sh[CC];
    sh[c] = m * m;
    __syncthreads();
    if (c < 256) sh[c] += sh[c + 256] + sh[c + 512];
    __syncthreads();
    for (int off = 128; off > 0; off >>= 1) {
        if (c < off) sh[c] += sh[c + off];
        __syncthreads();
    }
    __shared__ float rinv;
    if (c == 0) rinv = rsqrtf(fmaxf(sh[0], 1e-12f));
    __syncthreads();
    g_xnorm[b * CC + c] = m * rinv;
}

// ---------------------------------------------------------------------------
__global__ void key_norm_kernel(const float* __restrict__ pk) {
    int p = blockIdx.x;
    int c = threadIdx.x;
    float v = pk[(size_t)p * CC + c];

    __shared__ float sh[CC];
    sh[c] = v * v;
    __syncthreads();
    if (c < 256) sh[c] += sh[c + 256] + sh[c + 512];
    __syncthreads();
    for (int off = 128; off > 0; off >>= 1) {
        if (c < off) sh[c] += sh[c + off];
        __syncthreads();
    }
    __shared__ float rinv;
    if (c == 0) rinv = rsqrtf(fmaxf(sh[0], 1e-12f));
    __syncthreads();
    g_pnorm[p * CC + c] = v * rinv;
}

// ---------------------------------------------------------------------------
__global__ __launch_bounds__(256)
void sim_gemm_kernel(const float* __restrict__ A, const float* __restrict__ Bm,
                     float* __restrict__ Cm) {
    __shared__ float As[32][33];
    __shared__ float Bs[32][33];

    const int tid = threadIdx.x;
    const int tx = tid & 15;
    const int ty = tid >> 4;
    const int m0 = blockIdx.y * 32;
    const int n0 = blockIdx.x * 32;

    const int lrow = tid >> 3;
    const int lk   = (tid & 7) * 4;

    const float* ag = A  + (size_t)(m0 + lrow) * CC + lk;
    const float* bg = Bm + (size_t)(n0 + lrow) * CC + lk;

    float acc[2][2] = {{0.f,0.f},{0.f,0.f}};

    float4 pa = *(const float4*)(ag);
    float4 pb = *(const float4*)(bg);

    for (int kb = 0; kb < CC / 32; kb++) {
        __syncthreads();
        As[lrow][lk+0]=pa.x; As[lrow][lk+1]=pa.y; As[lrow][lk+2]=pa.z; As[lrow][lk+3]=pa.w;
        Bs[lrow][lk+0]=pb.x; Bs[lrow][lk+1]=pb.y; Bs[lrow][lk+2]=pb.z; Bs[lrow][lk+3]=pb.w;
        __syncthreads();
        if (kb + 1 < CC / 32) {
            pa = *(const float4*)(ag + (kb + 1) * 32);
            pb = *(const float4*)(bg + (kb + 1) * 32);
        }
        #pragma unroll
        for (int kk = 0; kk < 32; kk++) {
            float a0 = As[ty*2+0][kk], a1 = As[ty*2+1][kk];
            float b0 = Bs[tx*2+0][kk], b1 = Bs[tx*2+1][kk];
            acc[0][0] = fmaf(a0,b0,acc[0][0]);
            acc[0][1] = fmaf(a0,b1,acc[0][1]);
            acc[1][0] = fmaf(a1,b0,acc[1][0]);
            acc[1][1] = fmaf(a1,b1,acc[1][1]);
        }
    }
    #pragma unroll
    for (int i = 0; i < 2; i++)
        #pragma unroll
        for (int j = 0; j < 2; j++)
            Cm[(size_t)(m0 + ty*2 + i) * POOL + n0 + tx*2 + j] = acc[i][j];
}

// ---------------------------------------------------------------------------
__global__ void topk_kernel() {
    int b = blockIdx.x;
    int t = threadIdx.x;
    __shared__ float vals[POOL];
    __shared__ float rv[256];
    __shared__ int   ri[256];

    for (int p = t; p < POOL; p += 256) vals[p] = g_sim[b * POOL + p];
    __syncthreads();

    float tsum = 0.0f;
    for (int it = 0; it < KSEL; it++) {
        float bvv = -1e30f; int bii = 0x7fffffff;
        for (int p = t; p < POOL; p += 256) {
            float v = vals[p];
            if (v > bvv || (v == bvv && p < bii)) { bvv = v; bii = p; }
        }
        rv[t] = bvv; ri[t] = bii;
        __syncthreads();
        for (int off = 128; off > 0; off >>= 1) {
            if (t < off) {
                float v2 = rv[t + off]; int i2 = ri[t + off];
                if (v2 > rv[t] || (v2 == rv[t] && i2 < ri[t])) { rv[t] = v2; ri[t] = i2; }
            }
            __syncthreads();
        }
        if (t == 0) {
            g_idx[b * KSEL + it] = ri[0];
            tsum += rv[0];
            vals[ri[0]] = -1e30f;
        }
        __syncthreads();
    }
    if (t == 0) g_topsum[b] = tsum;
}

// ---------------------------------------------------------------------------
__global__ void reduce_sim_kernel(float* __restrict__ out) {
    __shared__ float sh[256];
    int t = threadIdx.x;
    sh[t] = g_topsum[t];
    __syncthreads();
    for (int off = 128; off > 0; off >>= 1) {
        if (t < off) sh[t] += sh[t + off];
        __syncthreads();
    }
    if (t == 0) out[PROMPTED_ELEMS] = sh[0] / (float)BB;
}

// ---------------------------------------------------------------------------
__global__ void gather_kernel(float* __restrict__ out) {
    int j = blockIdx.x;
    int b = blockIdx.y;
    int t = threadIdx.x;

    int pid = g_idx[b * KSEL + (j >> 3)];
    const float4* src = (const float4*)(g_proj + ((size_t)pid * PLEN + (j & 7)) * CC);
    float4 v = src[t];
    ((float4*)(out + ((size_t)b * OUTROWS + 1 + j) * CC))[t] = v;
}

// ---------------------------------------------------------------------------
extern "C" void kernel_launch(void* const* d_in, const int* in_sizes, int n_in,
                              void* d_out, int out_size) {
    const float* x_embed = (const float*)d_in[0];
    const float* prompt  = (const float*)d_in[1];
    const float* pkey    = (const float*)d_in[2];
    const float* proj_w  = (const float*)d_in[3];
    const float* proj_b  = (const float*)d_in[4];
    float* out = (float*)d_out;

    float *p_xnorm, *p_pnorm, *p_sim, *p_proj;
    __half *p_ah, *p_wh;
    cudaGetSymbolAddress((void**)&p_xnorm, g_xnorm);
    cudaGetSymbolAddress((void**)&p_pnorm, g_pnorm);
    cudaGetSymbolAddress((void**)&p_sim,   g_sim);
    cudaGetSymbolAddress((void**)&p_proj,  g_proj);
    cudaGetSymbolAddress((void**)&p_ah,    g_ah);
    cudaGetSymbolAddress((void**)&p_wh,    g_wh);

    // One-time resources (handles only; no device memory)
    static cudaStream_t sA = nullptr, sB = nullptr;
    static cudaEvent_t  evFork = nullptr, evProj = nullptr, evDone = nullptr;
    if (sA == nullptr) {
        cudaStreamCreateWithFlags(&sA, cudaStreamNonBlocking);
        cudaStreamCreateWithFlags(&sB, cudaStreamNonBlocking);
        cudaEventCreateWithFlags(&evFork, cudaEventDisableTiming);
        cudaEventCreateWithFlags(&evProj, cudaEventDisableTiming);
        cudaEventCreateWithFlags(&evDone, cudaEventDisableTiming);
        cudaFuncSetAttribute(proj_fp16_kernel,
                             cudaFuncAttributeMaxDynamicSharedMemorySize, PROJ_SMEM);
    }

    // ---- fork BOTH created streams off the capture-origin (legacy) stream.
    // No kernels go to stream 0, so legacy-stream implicit syncs can't
    // serialize the two branches.
    cudaEventRecord(evFork, 0);
    cudaStreamWaitEvent(sA, evFork, 0);
    cudaStreamWaitEvent(sB, evFork, 0);

    // ===== Stream A: tensor/L1-bound chain (f16 convs + proj) =====
    {
        int n8a = PROJ_M * CC / 8;
        f32_to_f16_kernel<<<(n8a + 255) / 256, 256, 0, sA>>>(prompt, p_ah, n8a);
        int n8w = CC * CC / 8;
        f32_to_f16_kernel<<<(n8w + 255) / 256, 256, 0, sA>>>(proj_w, p_wh, n8w);
        dim3 grid(CC / PBN, PROJ_M / PBM);
        proj_fp16_kernel<<<grid, 256, PROJ_SMEM, sA>>>(p_ah, p_wh, prompt, proj_b, p_proj);
        cudaEventRecord(evProj, sA);
    }

    // ===== Stream B: DRAM-bound critical path =====
    key_norm_kernel<<<POOL, CC, 0, sB>>>(pkey);
    {
        dim3 grid(NCHUNK, BB);
        copy_mean_kernel<<<grid, 192, 0, sB>>>(x_embed, out);
    }
    mean_finish_kernel<<<BB, CC, 0, sB>>>();
    {
        dim3 grid(POOL / 32, BB / 32);
        sim_gemm_kernel<<<grid, 256, 0, sB>>>(p_xnorm, p_pnorm, p_sim);
    }
    topk_kernel<<<BB, 256, 0, sB>>>();
    reduce_sim_kernel<<<1, 256, 0, sB>>>(out);

    // gather needs g_proj (stream A) and g_idx (stream B) -> run on sB
    cudaStreamWaitEvent(sB, evProj, 0);
    {
        dim3 grid(KSEL * PLEN, BB);
        gather_kernel<<<grid, 192, 0, sB>>>(out);
    }

    // ---- join everything back to the origin stream before capture ends ----
    cudaEventRecord(evDone, sB);
    cudaStreamWaitEvent(0, evDone, 0);
}